// round 6
// baseline (speedup 1.0000x reference)
#include <cuda_runtime.h>
#include <math.h>

// RoPE-2D: x[B=32, S=1024, H=16, D=64] fp32, grid_sizes[B,2] int32.
// Combined rotation: rot(i*th) ∘ rot(j*th) == rot((i+j)*th).
// Single kernel, no barrier, no smem. 8 float4/thread (MLP_p1=8), loads
// front-batched; sincos + rotate + store done in consumption order to
// keep register live ranges (and occupancy) in check.

#define F4_PER_ROW 16        // D=64 floats = 16 float4
#define S_LOG2 10
#define ROWS 8               // s-rows per block

__global__ void __launch_bounds__(256) rope2d_kernel(const float4* __restrict__ x,
                                                     const int* __restrict__ grid_sizes,
                                                     float4* __restrict__ out) {
    int tid = threadIdx.x;
    int f0 = blockIdx.x * (ROWS * 256) + tid;

    // ---- front-batch all 8 streaming loads (MLP_p1 = 8) ----
    float4 v0 = __ldcs(&x[f0]);
    float4 v1 = __ldcs(&x[f0 + 256]);
    float4 v2 = __ldcs(&x[f0 + 512]);
    float4 v3 = __ldcs(&x[f0 + 768]);
    float4 v4 = __ldcs(&x[f0 + 1024]);
    float4 v5 = __ldcs(&x[f0 + 1280]);
    float4 v6 = __ldcs(&x[f0 + 1536]);
    float4 v7 = __ldcs(&x[f0 + 1792]);

    // ---- positions for 8 consecutive s-rows (same b, same cols) ----
    unsigned row0 = blockIdx.x * ROWS;
    unsigned s = row0 & ((1u << S_LOG2) - 1u);
    unsigned b = row0 >> S_LOG2;
    unsigned cols = (unsigned)__ldg(&grid_sizes[2 * b + 1]);

    unsigned i = s / cols;                  // one division for all 8 rows
    unsigned j = s - i * cols;
    int pos[ROWS];
#pragma unroll
    for (int r = 0; r < ROWS; r++) {
        pos[r] = (int)(i + j);
        j++; if (j == cols) { j = 0; i++; }
    }

    // theta_k = 10000^(-k/32) = exp2(-k * log2(10000)/32)
    int t = tid & (F4_PER_ROW - 1);         // pairs k=2t, 2t+1
    const float C = 13.287712379549449f / 32.0f;   // log2(10000)/32
    const float R = 0.7498942093324559f;           // 10000^(-1/32)
    float th0 = exp2f(-(float)(2 * t) * C);
    float th1 = th0 * R;

#define ROTATE_STORE(v, p, off)                                   \
    do {                                                          \
        float ca, sa, cb, sb;                                     \
        __sincosf((float)(p) * th0, &sa, &ca);                    \
        __sincosf((float)(p) * th1, &sb, &cb);                    \
        float4 o;                                                 \
        o.x = fmaf((v).x, ca, -(v).y * sa);                       \
        o.y = fmaf((v).y, ca,  (v).x * sa);                       \
        o.z = fmaf((v).z, cb, -(v).w * sb);                       \
        o.w = fmaf((v).w, cb,  (v).z * sb);                       \
        __stcs(&out[f0 + (off)], o);                              \
    } while (0)

    ROTATE_STORE(v0, pos[0], 0);
    ROTATE_STORE(v1, pos[1], 256);
    ROTATE_STORE(v2, pos[2], 512);
    ROTATE_STORE(v3, pos[3], 768);
    ROTATE_STORE(v4, pos[4], 1024);
    ROTATE_STORE(v5, pos[5], 1280);
    ROTATE_STORE(v6, pos[6], 1536);
    ROTATE_STORE(v7, pos[7], 1792);
#undef ROTATE_STORE
}

extern "C" void kernel_launch(void* const* d_in, const int* in_sizes, int n_in,
                              void* d_out, int out_size) {
    const float4* x = (const float4*)d_in[0];
    const int* grid_sizes = (const int*)d_in[1];
    float4* out = (float4*)d_out;

    int total4 = in_sizes[0] / 4;                  // 8,388,608 float4
    int nblocks = total4 / (ROWS * 256);           // 4096 blocks
    rope2d_kernel<<<nblocks, 256>>>(x, grid_sizes, out);
}